// round 9
// baseline (speedup 1.0000x reference)
#include <cuda_runtime.h>
#include <cstdint>

typedef unsigned long long ull;

#define BB   128
#define D0   2048
#define NH1  2048
#define DOUT 512
#define MAXM (100 * BB)
#define KB   8

// ---------------- scratch (static device globals; no allocation) --------------
__device__ float g_cur [(size_t)MAXM * NH1];   // reused: CUR0 then CUR1
__device__ float g_cur2[(size_t)MAXM * DOUT];

// ---------------- packed fp32 helpers (Blackwell FFMA2 path) ------------------
__device__ __forceinline__ void fma2(ull& d, ull a, ull b) {
    asm("fma.rn.f32x2 %0, %1, %2, %0;" : "+l"(d) : "l"(a), "l"(b));
}
__device__ __forceinline__ ull add2v(ull a, ull b) {
    ull d;
    asm("add.rn.f32x2 %0, %1, %2;" : "=l"(d) : "l"(a), "l"(b));
    return d;
}
__device__ __forceinline__ ull dup2(float x) {
    ull d;
    asm("mov.b64 %0, {%1, %1};" : "=l"(d) : "f"(x));
    return d;
}

// ================== reference-exact split-K SGEMM =============================
// C[r, n] = sum_k A[r,k] * W[n,k] in the verified reference order:
//   4 contiguous K-chunks; ascending fp32 FMA chain inside each chunk;
//   chunk sums combined ascending. fma.rn.f32x2 = two independent exact fp32
//   FMAs, so the result is bit-faithful to the reference.
// Block tile 128(M) x 256(N); thread tile 8x16; chunk totals live in smem.
// mode 0: A row r maps to x[b = r%128][t = r/128][k]; else row-major.
__global__ __launch_bounds__(256, 1) void sgemm(
        int mode, int N, int K, int Tfull,
        const float* __restrict__ A, const float* __restrict__ W) {
    __shared__ float As[2][KB][128];
    __shared__ float Bs[2][KB][256];
    extern __shared__ ull tots[];          // [64][256] : per-thread chunk totals

    float* C = (mode == 2) ? g_cur2 : g_cur;

    const int tid = threadIdx.x;
    const int tx = tid & 15, ty = tid >> 4;
    const int bm = blockIdx.y * 128, bn = blockIdx.x * 256;

    // ---- gmem prefetch coords ----
    // A: 128 rows x 8 k = 1024 floats; thread -> row tid>>1, half q=tid&1
    const int arow = tid >> 1, aq = tid & 1;
    size_t baseA;
    {
        int row = bm + arow;
        if (mode == 0) {
            int b = row & (BB - 1);
            int t = row >> 7;
            baseA = ((size_t)b * Tfull + t) * (size_t)K + aq * 4;
        } else {
            baseA = (size_t)row * K + aq * 4;
        }
    }
    // B: 256 rows x 8 k; thread -> row tid, both halves
    const size_t baseB = (size_t)(bn + tid) * K;

    float4 pa, pb0, pb1;
    auto ldg_tile = [&](int kt) {
        pa  = *(const float4*)(A + baseA + kt * KB);
        pb0 = *(const float4*)(W + baseB + kt * KB);
        pb1 = *(const float4*)(W + baseB + kt * KB + 4);
    };
    auto sts_tile = [&](int s) {
        As[s][aq * 4 + 0][arow] = pa.x;
        As[s][aq * 4 + 1][arow] = pa.y;
        As[s][aq * 4 + 2][arow] = pa.z;
        As[s][aq * 4 + 3][arow] = pa.w;
        Bs[s][0][tid] = pb0.x; Bs[s][1][tid] = pb0.y;
        Bs[s][2][tid] = pb0.z; Bs[s][3][tid] = pb0.w;
        Bs[s][4][tid] = pb1.x; Bs[s][5][tid] = pb1.y;
        Bs[s][6][tid] = pb1.z; Bs[s][7][tid] = pb1.w;
    };

    ull acc[8][8];
    #pragma unroll
    for (int i = 0; i < 8; i++)
        #pragma unroll
        for (int j = 0; j < 8; j++) acc[i][j] = 0ull;

    const int nkt = K / KB;          // 256 tiles; chunk = 64 tiles
    const int ctile = nkt >> 2;

    ldg_tile(0);
    sts_tile(0);
    __syncthreads();

    int buf = 0;
    for (int kt = 0; kt < nkt; kt++) {
        if (kt + 1 < nkt) ldg_tile(kt + 1);

        #pragma unroll
        for (int kk = 0; kk < KB; kk++) {
            const float4 av0 = *(const float4*)&As[buf][kk][ty * 8];
            const float4 av1 = *(const float4*)&As[buf][kk][ty * 8 + 4];
            const ulonglong2 bv0 = *(const ulonglong2*)&Bs[buf][kk][tx * 16];
            const ulonglong2 bv1 = *(const ulonglong2*)&Bs[buf][kk][tx * 16 + 4];
            const ulonglong2 bv2 = *(const ulonglong2*)&Bs[buf][kk][tx * 16 + 8];
            const ulonglong2 bv3 = *(const ulonglong2*)&Bs[buf][kk][tx * 16 + 12];
            ull a[8];
            a[0] = dup2(av0.x); a[1] = dup2(av0.y);
            a[2] = dup2(av0.z); a[3] = dup2(av0.w);
            a[4] = dup2(av1.x); a[5] = dup2(av1.y);
            a[6] = dup2(av1.z); a[7] = dup2(av1.w);
            const ull b[8] = {bv0.x, bv0.y, bv1.x, bv1.y,
                              bv2.x, bv2.y, bv3.x, bv3.y};
            #pragma unroll
            for (int i = 0; i < 8; i++)
                #pragma unroll
                for (int j = 0; j < 8; j++)
                    fma2(acc[i][j], a[i], b[j]);   // ascending-k chain
        }

        if (kt + 1 < nkt) {
            sts_tile(buf ^ 1);
            __syncthreads();
        }

        if (((kt + 1) & (ctile - 1)) == 0) {       // chunk boundary
            const int ch = (kt + 1) >> 6;          // 1..4 after this chunk
            #pragma unroll
            for (int i = 0; i < 8; i++)
                #pragma unroll
                for (int j = 0; j < 8; j++) {
                    ull* slot = &tots[(i * 8 + j) * 256 + tid];
                    *slot = (ch == 1) ? acc[i][j]
                                      : add2v(*slot, acc[i][j]);  // ascending
                    acc[i][j] = 0ull;
                }
        }
        buf ^= 1;
    }

    // ---- epilogue: write chunk totals to C ----
    #pragma unroll
    for (int i = 0; i < 8; i++) {
        const int row = bm + ty * 8 + i;
        float* cr = C + (size_t)row * N + bn + tx * 16;
        #pragma unroll
        for (int j = 0; j < 8; j++)
            *(ull*)(cr + 2 * j) = tots[(i * 8 + j) * 256 + tid];
    }
}

// ---------------- LIF time scan (bit-faithful, verified R5/R7/R8) -------------
__global__ void scan_kernel(int layer, int T, const float* __restrict__ thp,
                            float* __restrict__ spk_rec, float* __restrict__ mem_rec) {
    const int H  = (layer == 2) ? DOUT : NH1;
    const int BH = BB * H;
    int i = blockIdx.x * blockDim.x + threadIdx.x;
    if (i >= BH) return;
    const float* cur = (layer == 2) ? g_cur2 : g_cur;
    const float th = *thp;
    float m = 0.0f;
    for (int t = 0; t < T; t++) {
        size_t off = (size_t)t * BH + i;
        float c = cur[off];
        float reset = (m - th > 0.0f) ? th : 0.0f;   // reset from PREVIOUS mem
        m = 0.5f * m + c - reset;
        float s = (m - th > 0.0f) ? 1.0f : 0.0f;
        mem_rec[off] = m;
        spk_rec[off] = s;
    }
}

// ---------------- launch ----------------
extern "C" void kernel_launch(void* const* d_in, const int* in_sizes, int n_in,
                              void* d_out, int out_size) {
    const float* x   = (const float*)d_in[0];
    const float* W0  = (const float*)d_in[1];
    const float* W1  = (const float*)d_in[2];
    const float* W2  = (const float*)d_in[3];
    const float* th0 = (const float*)d_in[4];
    const float* th1 = (const float*)d_in[5];
    const float* th2 = (const float*)d_in[6];
    float* out = (float*)d_out;

    const int Tfull = in_sizes[0] / (BB * D0);
    const int T = out_size / (BB * (2 * NH1 + 2 * NH1 + 2 * DOUT));
    const int M = T * BB;

    const size_t S1 = (size_t)T * BB * NH1;
    const size_t S2 = (size_t)T * BB * DOUT;
    float* spk0 = out;
    float* spk1 = out + S1;
    float* spk2 = out + 2 * S1;
    float* mem0 = out + 2 * S1 + S2;
    float* mem1 = out + 3 * S1 + S2;
    float* mem2 = out + 4 * S1 + S2;

    const int dsm = 64 * 256 * sizeof(ull);   // 131072 B chunk-total buffer
    cudaFuncSetAttribute(sgemm, cudaFuncAttributeMaxDynamicSharedMemorySize, dsm);

    dim3 g0(NH1 / 256, M / 128);
    sgemm<<<g0, 256, dsm>>>(0, NH1, D0, Tfull, x, W0);
    scan_kernel<<<(BB * NH1 + 255) / 256, 256>>>(0, T, th0, spk0, mem0);

    dim3 g1(NH1 / 256, M / 128);
    sgemm<<<g1, 256, dsm>>>(1, NH1, NH1, Tfull, spk0, W1);
    scan_kernel<<<(BB * NH1 + 255) / 256, 256>>>(1, T, th1, spk1, mem1);

    dim3 g2(DOUT / 256, M / 128);
    sgemm<<<g2, 256, dsm>>>(2, DOUT, NH1, Tfull, spk1, W2);
    scan_kernel<<<(BB * DOUT + 255) / 256, 256>>>(2, T, th2, spk2, mem2);
}

// round 10
// speedup vs baseline: 2.0255x; 2.0255x over previous
#include <cuda_runtime.h>
#include <cstdint>

typedef unsigned long long ull;

#define BB   128
#define D0   2048
#define NH1  2048
#define DOUT 512
#define MAXM (100 * BB)
#define KB   16

// ---------------- scratch (static device globals; no allocation) --------------
__device__ float g_cur [(size_t)MAXM * NH1];   // reused: CUR0 then CUR1
__device__ float g_cur2[(size_t)MAXM * DOUT];

// ---------------- packed fp32 helpers (Blackwell FFMA2 path) ------------------
__device__ __forceinline__ void fma2(ull& d, ull a, ull b) {
    asm("fma.rn.f32x2 %0, %1, %2, %0;" : "+l"(d) : "l"(a), "l"(b));
}
__device__ __forceinline__ void add2(ull& d, ull a) {
    asm("add.rn.f32x2 %0, %0, %1;" : "+l"(d) : "l"(a));
}
__device__ __forceinline__ ull dup2(float x) {
    ull d;
    asm("mov.b64 %0, {%1, %1};" : "=l"(d) : "f"(x));
    return d;
}

// ================== reference-exact split-K SGEMM =============================
// C[r, n] = sum_k A[r,k] * W[n,k] in the verified reference order:
//   4 contiguous K-chunks; ascending fp32 FMA chain inside each chunk;
//   chunk sums combined ascending (tot starts at +0; 0+c0 is exact).
//   fma.rn.f32x2 = two independent exact fp32 FMAs -> bit-faithful output.
// Block tile 128x128, 256 threads, thread tile 8x8.
// A stored PLAIN in smem; per-thread (a,a) packs built via mov.b64 (ALU pipe),
// halving LDS traffic vs the duplicated-A layout (R8) -> FMA-pipe bound.
// mode 0: A row r maps to x[b = r%128][t = r/128][k]; else row-major.
__global__ __launch_bounds__(256, 1) void sgemm(
        int mode, int N, int K, int Tfull,
        const float* __restrict__ A, const float* __restrict__ W) {
    __shared__ float As[2][KB][128];
    __shared__ float Bs[2][KB][128];

    float* C = (mode == 2) ? g_cur2 : g_cur;

    const int tid = threadIdx.x;
    const int tx = tid & 15, ty = tid >> 4;
    const int bm = blockIdx.y * 128, bn = blockIdx.x * 128;

    // ---- gmem prefetch coords: u in {tid, tid+256}: row = u>>2, q = u&3 ----
    size_t baseA[2], baseB[2];
    int rA[2], qq[2];
    #pragma unroll
    for (int i = 0; i < 2; i++) {
        int u = tid + i * 256;
        int r = u >> 2;
        qq[i] = u & 3;
        rA[i] = r;
        int row = bm + r;
        if (mode == 0) {
            int b = row & (BB - 1);
            int t = row >> 7;
            baseA[i] = ((size_t)b * Tfull + t) * (size_t)K;
        } else {
            baseA[i] = (size_t)row * K;
        }
        baseB[i] = (size_t)(bn + r) * K;
    }

    float4 pa[2], pb[2];
    auto ldg_tile = [&](int kt) {
        #pragma unroll
        for (int i = 0; i < 2; i++) {
            pa[i] = *(const float4*)(A + baseA[i] + kt * KB + qq[i] * 4);
            pb[i] = *(const float4*)(W + baseB[i] + kt * KB + qq[i] * 4);
        }
    };
    auto sts_tile = [&](int s) {
        #pragma unroll
        for (int i = 0; i < 2; i++) {
            const float va[4] = {pa[i].x, pa[i].y, pa[i].z, pa[i].w};
            const float vb[4] = {pb[i].x, pb[i].y, pb[i].z, pb[i].w};
            #pragma unroll
            for (int j = 0; j < 4; j++) {
                int kl = qq[i] * 4 + j;
                As[s][kl][rA[i]] = va[j];
                Bs[s][kl][rA[i]] = vb[j];
            }
        }
    };

    ull acc[8][4], tot[8][4];
    #pragma unroll
    for (int i = 0; i < 8; i++)
        #pragma unroll
        for (int j = 0; j < 4; j++) { acc[i][j] = 0ull; tot[i][j] = 0ull; }

    const int nkt = K / KB;          // 128 k-tiles; chunk = 32 tiles
    const int ctile = nkt >> 2;

    ldg_tile(0);
    sts_tile(0);
    __syncthreads();

    int buf = 0;
    for (int kt = 0; kt < nkt; kt++) {
        if (kt + 1 < nkt) ldg_tile(kt + 1);

        #pragma unroll
        for (int kk = 0; kk < KB; kk++) {
            const float4 av0 = *(const float4*)&As[buf][kk][ty * 4];
            const float4 av1 = *(const float4*)&As[buf][kk][64 + ty * 4];
            const ulonglong2 bv0 = *(const ulonglong2*)&Bs[buf][kk][tx * 4];
            const ulonglong2 bv1 = *(const ulonglong2*)&Bs[buf][kk][64 + tx * 4];
            ull a[8];
            a[0] = dup2(av0.x); a[1] = dup2(av0.y);
            a[2] = dup2(av0.z); a[3] = dup2(av0.w);
            a[4] = dup2(av1.x); a[5] = dup2(av1.y);
            a[6] = dup2(av1.z); a[7] = dup2(av1.w);
            const ull b[4] = {bv0.x, bv0.y, bv1.x, bv1.y};
            #pragma unroll
            for (int i = 0; i < 8; i++)
                #pragma unroll
                for (int j = 0; j < 4; j++)
                    fma2(acc[i][j], a[i], b[j]);   // ascending-k chain
        }

        if (kt + 1 < nkt) {
            sts_tile(buf ^ 1);
            __syncthreads();
        }

        if (((kt + 1) & (ctile - 1)) == 0) {       // chunk boundary
            #pragma unroll
            for (int i = 0; i < 8; i++)
                #pragma unroll
                for (int j = 0; j < 4; j++) {
                    add2(tot[i][j], acc[i][j]);    // ascending chunk combine
                    acc[i][j] = 0ull;
                }
        }
        buf ^= 1;
    }

    #pragma unroll
    for (int i = 0; i < 8; i++) {
        int row = bm + ((i < 4) ? (ty * 4 + i) : (64 + ty * 4 + (i - 4)));
        float* cr = C + (size_t)row * N + bn;
        #pragma unroll
        for (int j = 0; j < 4; j++) {
            int col = (j < 2) ? (tx * 4 + j * 2) : (64 + tx * 4 + (j - 2) * 2);
            *(ull*)(cr + col) = tot[i][j];
        }
    }
}

// ---------------- LIF time scan (bit-faithful, verified R5/R7/R8) -------------
__global__ void scan_kernel(int layer, int T, const float* __restrict__ thp,
                            float* __restrict__ spk_rec, float* __restrict__ mem_rec) {
    const int H  = (layer == 2) ? DOUT : NH1;
    const int BH = BB * H;
    int i = blockIdx.x * blockDim.x + threadIdx.x;
    if (i >= BH) return;
    const float* cur = (layer == 2) ? g_cur2 : g_cur;
    const float th = *thp;
    float m = 0.0f;
    for (int t = 0; t < T; t++) {
        size_t off = (size_t)t * BH + i;
        float c = cur[off];
        float reset = (m - th > 0.0f) ? th : 0.0f;   // reset from PREVIOUS mem
        m = 0.5f * m + c - reset;
        float s = (m - th > 0.0f) ? 1.0f : 0.0f;
        mem_rec[off] = m;
        spk_rec[off] = s;
    }
}

// ---------------- launch ----------------
extern "C" void kernel_launch(void* const* d_in, const int* in_sizes, int n_in,
                              void* d_out, int out_size) {
    const float* x   = (const float*)d_in[0];
    const float* W0  = (const float*)d_in[1];
    const float* W1  = (const float*)d_in[2];
    const float* W2  = (const float*)d_in[3];
    const float* th0 = (const float*)d_in[4];
    const float* th1 = (const float*)d_in[5];
    const float* th2 = (const float*)d_in[6];
    float* out = (float*)d_out;

    const int Tfull = in_sizes[0] / (BB * D0);
    const int T = out_size / (BB * (2 * NH1 + 2 * NH1 + 2 * DOUT));
    const int M = T * BB;

    const size_t S1 = (size_t)T * BB * NH1;
    const size_t S2 = (size_t)T * BB * DOUT;
    float* spk0 = out;
    float* spk1 = out + S1;
    float* spk2 = out + 2 * S1;
    float* mem0 = out + 2 * S1 + S2;
    float* mem1 = out + 3 * S1 + S2;
    float* mem2 = out + 4 * S1 + S2;

    dim3 g0(NH1 / 128, M / 128);
    sgemm<<<g0, 256>>>(0, NH1, D0, Tfull, x, W0);
    scan_kernel<<<(BB * NH1 + 255) / 256, 256>>>(0, T, th0, spk0, mem0);

    dim3 g1(NH1 / 128, M / 128);
    sgemm<<<g1, 256>>>(1, NH1, NH1, Tfull, spk0, W1);
    scan_kernel<<<(BB * NH1 + 255) / 256, 256>>>(1, T, th1, spk1, mem1);

    dim3 g2(DOUT / 128, M / 128);
    sgemm<<<g2, 256>>>(2, DOUT, NH1, Tfull, spk1, W2);
    scan_kernel<<<(BB * DOUT + 255) / 256, 256>>>(2, T, th2, spk2, mem2);
}

// round 11
// speedup vs baseline: 2.0663x; 1.0201x over previous
#include <cuda_runtime.h>
#include <cstdint>

typedef unsigned long long ull;

#define BB   128
#define D0   2048
#define NH1  2048
#define DOUT 512
#define MAXM (100 * BB)
#define KB   16

// ---------------- scratch (static device globals; no allocation) --------------
__device__ float g_cur [(size_t)MAXM * NH1];   // reused: CUR0 then CUR1
__device__ float g_cur2[(size_t)MAXM * DOUT];

// ---------------- packed fp32 helpers (Blackwell FFMA2 path) ------------------
__device__ __forceinline__ void fma2(ull& d, ull a, ull b) {
    asm("fma.rn.f32x2 %0, %1, %2, %0;" : "+l"(d) : "l"(a), "l"(b));
}
__device__ __forceinline__ ull add2v(ull a, ull b) {
    ull d;
    asm("add.rn.f32x2 %0, %1, %2;" : "=l"(d) : "l"(a), "l"(b));
    return d;
}
__device__ __forceinline__ ull dup2(float x) {
    ull d;
    asm("mov.b64 %0, {%1, %1};" : "=l"(d) : "f"(x));
    return d;
}

// ================== reference-exact split-K SGEMM =============================
// C[r, n] = sum_k A[r,k] * W[n,k] in the verified reference order:
//   4 contiguous K-chunks; ascending fp32 FMA chain inside each chunk;
//   chunk sums combined ascending. fma.rn.f32x2 = two independent exact fp32
//   FMAs -> bit-faithful output (rel_err 0.0 measured R8/R10).
// Block tile 128x128, 256 threads, thread tile 8x8.
// Chunk totals live in SMEM (touched only at 4 chunk boundaries) to keep
// registers ~128 -> 2 CTAs/SM for latency hiding.
// mode 0: A row r maps to x[b = r%128][t = r/128][k]; else row-major.
__global__ __launch_bounds__(256, 2) void sgemm(
        int mode, int N, int K, int Tfull,
        const float* __restrict__ A, const float* __restrict__ W) {
    __shared__ float As[2][KB][128];   // 16 KB
    __shared__ float Bs[2][KB][128];   // 16 KB
    extern __shared__ ull tots[];      // [32][256] = 64 KB chunk totals

    float* C = (mode == 2) ? g_cur2 : g_cur;

    const int tid = threadIdx.x;
    const int tx = tid & 15, ty = tid >> 4;
    const int bm = blockIdx.y * 128, bn = blockIdx.x * 128;

    // ---- gmem prefetch coords: u in {tid, tid+256}: row = u>>2, q = u&3 ----
    size_t baseA[2], baseB[2];
    int rA[2], qq[2];
    #pragma unroll
    for (int i = 0; i < 2; i++) {
        int u = tid + i * 256;
        int r = u >> 2;
        qq[i] = u & 3;
        rA[i] = r;
        int row = bm + r;
        if (mode == 0) {
            int b = row & (BB - 1);
            int t = row >> 7;
            baseA[i] = ((size_t)b * Tfull + t) * (size_t)K;
        } else {
            baseA[i] = (size_t)row * K;
        }
        baseB[i] = (size_t)(bn + r) * K;
    }

    float4 pa[2], pb[2];
    auto ldg_tile = [&](int kt) {
        #pragma unroll
        for (int i = 0; i < 2; i++) {
            pa[i] = *(const float4*)(A + baseA[i] + kt * KB + qq[i] * 4);
            pb[i] = *(const float4*)(W + baseB[i] + kt * KB + qq[i] * 4);
        }
    };
    auto sts_tile = [&](int s) {
        #pragma unroll
        for (int i = 0; i < 2; i++) {
            const float va[4] = {pa[i].x, pa[i].y, pa[i].z, pa[i].w};
            const float vb[4] = {pb[i].x, pb[i].y, pb[i].z, pb[i].w};
            #pragma unroll
            for (int j = 0; j < 4; j++) {
                int kl = qq[i] * 4 + j;
                As[s][kl][rA[i]] = va[j];
                Bs[s][kl][rA[i]] = vb[j];
            }
        }
    };

    ull acc[8][4];
    #pragma unroll
    for (int i = 0; i < 8; i++)
        #pragma unroll
        for (int j = 0; j < 4; j++) acc[i][j] = 0ull;

    const int nkt = K / KB;          // 128 k-tiles; chunk = 32 tiles
    const int ctile = nkt >> 2;

    ldg_tile(0);
    sts_tile(0);
    __syncthreads();

    int buf = 0;
    for (int kt = 0; kt < nkt; kt++) {
        if (kt + 1 < nkt) ldg_tile(kt + 1);

        #pragma unroll
        for (int kk = 0; kk < KB; kk++) {
            const float4 av0 = *(const float4*)&As[buf][kk][ty * 4];
            const float4 av1 = *(const float4*)&As[buf][kk][64 + ty * 4];
            const ulonglong2 bv0 = *(const ulonglong2*)&Bs[buf][kk][tx * 4];
            const ulonglong2 bv1 = *(const ulonglong2*)&Bs[buf][kk][64 + tx * 4];
            ull a[8];
            a[0] = dup2(av0.x); a[1] = dup2(av0.y);
            a[2] = dup2(av0.z); a[3] = dup2(av0.w);
            a[4] = dup2(av1.x); a[5] = dup2(av1.y);
            a[6] = dup2(av1.z); a[7] = dup2(av1.w);
            const ull b[4] = {bv0.x, bv0.y, bv1.x, bv1.y};
            #pragma unroll
            for (int i = 0; i < 8; i++)
                #pragma unroll
                for (int j = 0; j < 4; j++)
                    fma2(acc[i][j], a[i], b[j]);   // ascending-k chain
        }

        if (kt + 1 < nkt) {
            sts_tile(buf ^ 1);
            __syncthreads();
        }

        if (((kt + 1) & (ctile - 1)) == 0) {       // chunk boundary
            const bool first = (kt + 1) == ctile;
            #pragma unroll
            for (int i = 0; i < 8; i++)
                #pragma unroll
                for (int j = 0; j < 4; j++) {
                    ull* slot = &tots[(i * 4 + j) * 256 + tid];
                    *slot = first ? acc[i][j]
                                  : add2v(*slot, acc[i][j]);  // ascending combine
                    acc[i][j] = 0ull;
                }
        }
        buf ^= 1;
    }

    // ---- epilogue: write chunk totals (smem) to C ----
    #pragma unroll
    for (int i = 0; i < 8; i++) {
        int row = bm + ((i < 4) ? (ty * 4 + i) : (64 + ty * 4 + (i - 4)));
        float* cr = C + (size_t)row * N + bn;
        #pragma unroll
        for (int j = 0; j < 4; j++) {
            int col = (j < 2) ? (tx * 4 + j * 2) : (64 + tx * 4 + (j - 2) * 2);
            *(ull*)(cr + col) = tots[(i * 4 + j) * 256 + tid];
        }
    }
}

// ---------------- LIF time scan (bit-faithful; float2 vectorized) -------------
__global__ void scan_kernel(int layer, int T, const float* __restrict__ thp,
                            float* __restrict__ spk_rec, float* __restrict__ mem_rec) {
    const int H  = (layer == 2) ? DOUT : NH1;
    const int BH = BB * H;
    int p = blockIdx.x * blockDim.x + threadIdx.x;
    if (p >= (BH >> 1)) return;
    const int i = p << 1;
    const float* cur = (layer == 2) ? g_cur2 : g_cur;
    const float th = *thp;
    float m0 = 0.0f, m1 = 0.0f;
    for (int t = 0; t < T; t++) {
        size_t off = (size_t)t * BH + i;
        float2 c = *(const float2*)(cur + off);
        float r0 = (m0 - th > 0.0f) ? th : 0.0f;   // reset from PREVIOUS mem
        float r1 = (m1 - th > 0.0f) ? th : 0.0f;
        m0 = 0.5f * m0 + c.x - r0;
        m1 = 0.5f * m1 + c.y - r1;
        float s0 = (m0 - th > 0.0f) ? 1.0f : 0.0f;
        float s1 = (m1 - th > 0.0f) ? 1.0f : 0.0f;
        *(float2*)(mem_rec + off) = make_float2(m0, m1);
        *(float2*)(spk_rec + off) = make_float2(s0, s1);
    }
}

// ---------------- launch ----------------
extern "C" void kernel_launch(void* const* d_in, const int* in_sizes, int n_in,
                              void* d_out, int out_size) {
    const float* x   = (const float*)d_in[0];
    const float* W0  = (const float*)d_in[1];
    const float* W1  = (const float*)d_in[2];
    const float* W2  = (const float*)d_in[3];
    const float* th0 = (const float*)d_in[4];
    const float* th1 = (const float*)d_in[5];
    const float* th2 = (const float*)d_in[6];
    float* out = (float*)d_out;

    const int Tfull = in_sizes[0] / (BB * D0);
    const int T = out_size / (BB * (2 * NH1 + 2 * NH1 + 2 * DOUT));
    const int M = T * BB;

    const size_t S1 = (size_t)T * BB * NH1;
    const size_t S2 = (size_t)T * BB * DOUT;
    float* spk0 = out;
    float* spk1 = out + S1;
    float* spk2 = out + 2 * S1;
    float* mem0 = out + 2 * S1 + S2;
    float* mem1 = out + 3 * S1 + S2;
    float* mem2 = out + 4 * S1 + S2;

    const int dsm = 32 * 256 * sizeof(ull);   // 65536 B chunk-total buffer
    cudaFuncSetAttribute(sgemm, cudaFuncAttributeMaxDynamicSharedMemorySize, dsm);

    dim3 g0(NH1 / 128, M / 128);
    sgemm<<<g0, 256, dsm>>>(0, NH1, D0, Tfull, x, W0);
    scan_kernel<<<(BB * NH1 / 2 + 255) / 256, 256>>>(0, T, th0, spk0, mem0);

    dim3 g1(NH1 / 128, M / 128);
    sgemm<<<g1, 256, dsm>>>(1, NH1, NH1, Tfull, spk0, W1);
    scan_kernel<<<(BB * NH1 / 2 + 255) / 256, 256>>>(1, T, th1, spk1, mem1);

    dim3 g2(DOUT / 128, M / 128);
    sgemm<<<g2, 256, dsm>>>(2, DOUT, NH1, Tfull, spk1, W2);
    scan_kernel<<<(BB * DOUT / 2 + 255) / 256, 256>>>(2, T, th2, spk2, mem2);
}

// round 12
// speedup vs baseline: 2.2043x; 1.0668x over previous
#include <cuda_runtime.h>
#include <cstdint>

typedef unsigned long long ull;

#define BB   128
#define D0   2048
#define NH1  2048
#define DOUT 512
#define MAXM (100 * BB)
#define KB   16
#define STR  132   // padded smem row stride (floats): kills 4-way STS conflicts,
                   // keeps 16B alignment for float4/ulonglong2 mainloop reads

// ---------------- scratch (static device globals; no allocation) --------------
__device__ float g_cur [(size_t)MAXM * NH1];   // reused: CUR0 then CUR1
__device__ float g_cur2[(size_t)MAXM * DOUT];

// ---------------- packed fp32 helpers (Blackwell FFMA2 path) ------------------
__device__ __forceinline__ void fma2(ull& d, ull a, ull b) {
    asm("fma.rn.f32x2 %0, %1, %2, %0;" : "+l"(d) : "l"(a), "l"(b));
}
__device__ __forceinline__ ull add2v(ull a, ull b) {
    ull d;
    asm("add.rn.f32x2 %0, %1, %2;" : "=l"(d) : "l"(a), "l"(b));
    return d;
}
__device__ __forceinline__ ull dup2(float x) {
    ull d;
    asm("mov.b64 %0, {%1, %1};" : "=l"(d) : "f"(x));
    return d;
}

// ================== reference-exact split-K SGEMM =============================
// C[r, n] = sum_k A[r,k] * W[n,k] in the verified reference order:
//   4 contiguous K-chunks; ascending fp32 FMA chain inside each chunk;
//   chunk sums combined ascending. fma.rn.f32x2 = two independent exact fp32
//   FMAs -> bit-faithful output (rel_err 0.0 measured R8/R10/R11).
// Block tile 128x128, 256 threads, thread tile 8x8; chunk totals in SMEM;
// 2 CTAs/SM. mode 0: A row r maps to x[b = r%128][t = r/128][k].
__global__ __launch_bounds__(256, 2) void sgemm(
        int mode, int N, int K, int Tfull,
        const float* __restrict__ A, const float* __restrict__ W) {
    __shared__ float As[2][KB][STR];   // 16.9 KB
    __shared__ float Bs[2][KB][STR];   // 16.9 KB
    extern __shared__ ull tots[];      // [32][256] = 64 KB chunk totals

    float* C = (mode == 2) ? g_cur2 : g_cur;

    const int tid = threadIdx.x;
    const int tx = tid & 15, ty = tid >> 4;
    const int bm = blockIdx.y * 128, bn = blockIdx.x * 128;

    // ---- gmem prefetch coords: u in {tid, tid+256}: row = u>>2, q = u&3 ----
    size_t baseA[2], baseB[2];
    int rA[2], qq[2];
    #pragma unroll
    for (int i = 0; i < 2; i++) {
        int u = tid + i * 256;
        int r = u >> 2;
        qq[i] = u & 3;
        rA[i] = r;
        int row = bm + r;
        if (mode == 0) {
            int b = row & (BB - 1);
            int t = row >> 7;
            baseA[i] = ((size_t)b * Tfull + t) * (size_t)K;
        } else {
            baseA[i] = (size_t)row * K;
        }
        baseB[i] = (size_t)(bn + r) * K;
    }

    float4 pa[2], pb[2];
    auto ldg_tile = [&](int kt) {
        #pragma unroll
        for (int i = 0; i < 2; i++) {
            pa[i] = *(const float4*)(A + baseA[i] + kt * KB + qq[i] * 4);
            pb[i] = *(const float4*)(W + baseB[i] + kt * KB + qq[i] * 4);
        }
    };
    auto sts_tile = [&](int s) {
        #pragma unroll
        for (int i = 0; i < 2; i++) {
            const float va[4] = {pa[i].x, pa[i].y, pa[i].z, pa[i].w};
            const float vb[4] = {pb[i].x, pb[i].y, pb[i].z, pb[i].w};
            #pragma unroll
            for (int j = 0; j < 4; j++) {
                int kl = qq[i] * 4 + j;
                As[s][kl][rA[i]] = va[j];
                Bs[s][kl][rA[i]] = vb[j];
            }
        }
    };

    ull acc[8][4];
    #pragma unroll
    for (int i = 0; i < 8; i++)
        #pragma unroll
        for (int j = 0; j < 4; j++) acc[i][j] = 0ull;

    const int nkt = K / KB;          // 128 k-tiles; chunk = 32 tiles
    const int ctile = nkt >> 2;

    ldg_tile(0);
    sts_tile(0);
    __syncthreads();

    int buf = 0;
    for (int kt = 0; kt < nkt; kt++) {
        if (kt + 1 < nkt) ldg_tile(kt + 1);

        #pragma unroll
        for (int kk = 0; kk < KB; kk++) {
            const float4 av0 = *(const float4*)&As[buf][kk][ty * 4];
            const float4 av1 = *(const float4*)&As[buf][kk][64 + ty * 4];
            const ulonglong2 bv0 = *(const ulonglong2*)&Bs[buf][kk][tx * 4];
            const ulonglong2 bv1 = *(const ulonglong2*)&Bs[buf][kk][64 + tx * 4];
            ull a[8];
            a[0] = dup2(av0.x); a[1] = dup2(av0.y);
            a[2] = dup2(av0.z); a[3] = dup2(av0.w);
            a[4] = dup2(av1.x); a[5] = dup2(av1.y);
            a[6] = dup2(av1.z); a[7] = dup2(av1.w);
            const ull b[4] = {bv0.x, bv0.y, bv1.x, bv1.y};
            #pragma unroll
            for (int i = 0; i < 8; i++)
                #pragma unroll
                for (int j = 0; j < 4; j++)
                    fma2(acc[i][j], a[i], b[j]);   // ascending-k chain
        }

        if (kt + 1 < nkt) {
            sts_tile(buf ^ 1);
            __syncthreads();
        }

        if (((kt + 1) & (ctile - 1)) == 0) {       // chunk boundary
            const bool first = (kt + 1) == ctile;
            #pragma unroll
            for (int i = 0; i < 8; i++)
                #pragma unroll
                for (int j = 0; j < 4; j++) {
                    ull* slot = &tots[(i * 4 + j) * 256 + tid];
                    *slot = first ? acc[i][j]
                                  : add2v(*slot, acc[i][j]);  // ascending combine
                    acc[i][j] = 0ull;
                }
        }
        buf ^= 1;
    }

    // ---- epilogue: write chunk totals (smem) to C ----
    #pragma unroll
    for (int i = 0; i < 8; i++) {
        int row = bm + ((i < 4) ? (ty * 4 + i) : (64 + ty * 4 + (i - 4)));
        float* cr = C + (size_t)row * N + bn;
        #pragma unroll
        for (int j = 0; j < 4; j++) {
            int col = (j < 2) ? (tx * 4 + j * 2) : (64 + tx * 4 + (j - 2) * 2);
            *(ull*)(cr + col) = tots[(i * 4 + j) * 256 + tid];
        }
    }
}

// ---------------- LIF time scan (bit-faithful; float4 vectorized) -------------
__global__ void scan_kernel(int layer, int T, const float* __restrict__ thp,
                            float* __restrict__ spk_rec, float* __restrict__ mem_rec) {
    const int H  = (layer == 2) ? DOUT : NH1;
    const int BH = BB * H;
    int p = blockIdx.x * blockDim.x + threadIdx.x;
    if (p >= (BH >> 2)) return;
    const int i = p << 2;
    const float* cur = (layer == 2) ? g_cur2 : g_cur;
    const float th = *thp;
    float m[4] = {0.0f, 0.0f, 0.0f, 0.0f};
    for (int t = 0; t < T; t++) {
        size_t off = (size_t)t * BH + i;
        float4 c = *(const float4*)(cur + off);
        const float cv[4] = {c.x, c.y, c.z, c.w};
        float s[4];
        #pragma unroll
        for (int e = 0; e < 4; e++) {
            float r = (m[e] - th > 0.0f) ? th : 0.0f;   // reset from PREVIOUS mem
            m[e] = 0.5f * m[e] + cv[e] - r;
            s[e] = (m[e] - th > 0.0f) ? 1.0f : 0.0f;
        }
        *(float4*)(mem_rec + off) = make_float4(m[0], m[1], m[2], m[3]);
        *(float4*)(spk_rec + off) = make_float4(s[0], s[1], s[2], s[3]);
    }
}

// ---------------- launch ----------------
extern "C" void kernel_launch(void* const* d_in, const int* in_sizes, int n_in,
                              void* d_out, int out_size) {
    const float* x   = (const float*)d_in[0];
    const float* W0  = (const float*)d_in[1];
    const float* W1  = (const float*)d_in[2];
    const float* W2  = (const float*)d_in[3];
    const float* th0 = (const float*)d_in[4];
    const float* th1 = (const float*)d_in[5];
    const float* th2 = (const float*)d_in[6];
    float* out = (float*)d_out;

    const int Tfull = in_sizes[0] / (BB * D0);
    const int T = out_size / (BB * (2 * NH1 + 2 * NH1 + 2 * DOUT));
    const int M = T * BB;

    const size_t S1 = (size_t)T * BB * NH1;
    const size_t S2 = (size_t)T * BB * DOUT;
    float* spk0 = out;
    float* spk1 = out + S1;
    float* spk2 = out + 2 * S1;
    float* mem0 = out + 2 * S1 + S2;
    float* mem1 = out + 3 * S1 + S2;
    float* mem2 = out + 4 * S1 + S2;

    const int dsm = 32 * 256 * sizeof(ull);   // 65536 B chunk-total buffer
    cudaFuncSetAttribute(sgemm, cudaFuncAttributeMaxDynamicSharedMemorySize, dsm);

    dim3 g0(NH1 / 128, M / 128);
    sgemm<<<g0, 256, dsm>>>(0, NH1, D0, Tfull, x, W0);
    scan_kernel<<<(BB * NH1 / 4 + 255) / 256, 256>>>(0, T, th0, spk0, mem0);

    dim3 g1(NH1 / 128, M / 128);
    sgemm<<<g1, 256, dsm>>>(1, NH1, NH1, Tfull, spk0, W1);
    scan_kernel<<<(BB * NH1 / 4 + 255) / 256, 256>>>(1, T, th1, spk1, mem1);

    dim3 g2(DOUT / 128, M / 128);
    sgemm<<<g2, 256, dsm>>>(2, DOUT, NH1, Tfull, spk1, W2);
    scan_kernel<<<(BB * DOUT / 4 + 255) / 256, 256>>>(2, T, th2, spk2, mem2);
}